// round 1
// baseline (speedup 1.0000x reference)
#include <cuda_runtime.h>
#include <cstdint>

#define B_  8
#define F_  512
#define K_  8
#define N_  2048
#define FKN (F_*K_*N_)   // per-batch element stride = 8388608
#define KN  (K_*N_)      // per-channel stride = 16384

typedef unsigned long long u64;

__device__ __forceinline__ u64 pack2(float a) {
    u64 r;
    asm("mov.b64 %0, {%1, %1};" : "=l"(r) : "f"(a));
    return r;
}
__device__ __forceinline__ void fma2(u64& d, u64 a, u64 b) {
    asm("fma.rn.f32x2 %0, %1, %2, %0;" : "+l"(d) : "l"(a), "l"(b));
}
__device__ __forceinline__ float2 unpack2(u64 v) {
    float lo, hi;
    asm("mov.b64 {%0, %1}, %2;" : "=f"(lo), "=f"(hi) : "l"(v));
    return make_float2(lo, hi);
}

// Fused kernel:
//   d[b,g,k,n] = sum_f W[g,f] * x[b,f,k,n]
//   kf[b,g,n]  = x[b,g,:,n]^T G d[b,g,:,n]   (G = Killing Gram, sparse, hardcoded)
//   out        = (kf<=0) ? x : x + kf*d
//
// CTA: b = blockIdx.z, g-rows [g0, g0+64), n-cols [n0, n0+32), all 8 k.
// 256 threads: lane = n index (0..31), wrow = t>>5 (0..7).
// Thread owns 8 g-rows (g0 + r*8 + wrow) x 8 k x 1 n => 32 f32x2 accumulators.
__global__ void __launch_bounds__(256, 2)
lnkr_fused_kernel(const float* __restrict__ x,
                  const float* __restrict__ W,
                  float* __restrict__ out)
{
    __shared__ float Ws[16][64];      // Ws[f_local][g_local]  (W transposed)
    __shared__ float Xs[16][32][10];  // Xs[f_local][n_local][k], padded 8->10

    const int t    = threadIdx.x;
    const int lane = t & 31;   // n within tile
    const int wrow = t >> 5;   // 0..7: k for loads, g sub-row for compute
    const int b    = blockIdx.z;
    const int g0   = blockIdx.y * 64;
    const int n0   = blockIdx.x * 32;

    // Global load pointers
    // W tile: thread loads float4 of row (g0 + t>>2), cols f0 + (t&3)*4 .. +3
    const float* wg = W + (size_t)(g0 + (t >> 2)) * F_ + ((t & 3) << 2);
    // X tile: thread loads 16 scalars: channels f0..f0+15 at fixed (k=wrow, n=n0+lane)
    const float* xg = x + (size_t)b * FKN + (size_t)wrow * N_ + n0 + lane;

    u64 acc[8][4];
#pragma unroll
    for (int r = 0; r < 8; ++r)
#pragma unroll
        for (int kp = 0; kp < 4; ++kp) acc[r][kp] = 0ull;

    float4 wreg;
    float  xreg[16];

    // Prefetch + store tile 0
    wreg = *(const float4*)(wg);
#pragma unroll
    for (int j = 0; j < 16; ++j) xreg[j] = xg[(size_t)j * KN];
    {
        const int fl0 = (t & 3) * 4, gl = t >> 2;
        Ws[fl0 + 0][gl] = wreg.x; Ws[fl0 + 1][gl] = wreg.y;
        Ws[fl0 + 2][gl] = wreg.z; Ws[fl0 + 3][gl] = wreg.w;
#pragma unroll
        for (int j = 0; j < 16; ++j) Xs[j][lane][wrow] = xreg[j];
    }
    __syncthreads();

    for (int tile = 0; tile < 32; ++tile) {
        // Prefetch next tile into registers (latency hidden under compute)
        if (tile < 31) {
            const int f0 = (tile + 1) * 16;
            wreg = *(const float4*)(wg + f0);
#pragma unroll
            for (int j = 0; j < 16; ++j) xreg[j] = xg[(size_t)(f0 + j) * KN];
        }

        // Compute on current smem tile
#pragma unroll
        for (int fl = 0; fl < 16; ++fl) {
            u64 wp[8];
#pragma unroll
            for (int r = 0; r < 8; ++r)
                wp[r] = pack2(Ws[fl][r * 8 + wrow]);   // lane-uniform -> broadcast LDS

            u64 xv[4];
            const u64* xp = (const u64*)(&Xs[fl][lane][0]);  // 8B-aligned (10 floats/row)
#pragma unroll
            for (int kp = 0; kp < 4; ++kp) xv[kp] = xp[kp];

#pragma unroll
            for (int r = 0; r < 8; ++r)
#pragma unroll
                for (int kp = 0; kp < 4; ++kp)
                    fma2(acc[r][kp], xv[kp], wp[r]);
        }
        __syncthreads();

        if (tile < 31) {
            const int fl0 = (t & 3) * 4, gl = t >> 2;
            Ws[fl0 + 0][gl] = wreg.x; Ws[fl0 + 1][gl] = wreg.y;
            Ws[fl0 + 2][gl] = wreg.z; Ws[fl0 + 3][gl] = wreg.w;
#pragma unroll
            for (int j = 0; j < 16; ++j) Xs[j][lane][wrow] = xreg[j];
            __syncthreads();
        }
    }

    // Epilogue: per owned g-row, reload x vector over k, Killing form, gated update.
#pragma unroll
    for (int r = 0; r < 8; ++r) {
        const int g = g0 + r * 8 + wrow;
        const size_t base = (size_t)b * FKN + (size_t)g * KN + n0 + lane;

        float xs[8];
#pragma unroll
        for (int k = 0; k < 8; ++k) xs[k] = x[base + (size_t)k * N_];

        float d[8];
#pragma unroll
        for (int kp = 0; kp < 4; ++kp) {
            float2 v = unpack2(acc[r][kp]);
            d[2 * kp] = v.x; d[2 * kp + 1] = v.y;
        }

        // kf = x^T G d with G_ab = 6 tr(E_a E_b) (sl(3) Chevalley basis):
        // nonzeros: G00=G44=12, G04=G40=-6, G13=G31=G26=G62=G57=G75=6
        const float kf = 6.0f * (2.0f * xs[0] * d[0] + 2.0f * xs[4] * d[4]
                                 - xs[0] * d[4] - xs[4] * d[0]
                                 + xs[1] * d[3] + xs[3] * d[1]
                                 + xs[2] * d[6] + xs[6] * d[2]
                                 + xs[5] * d[7] + xs[7] * d[5]);

#pragma unroll
        for (int k = 0; k < 8; ++k)
            out[base + (size_t)k * N_] = (kf <= 0.0f) ? xs[k] : fmaf(kf, d[k], xs[k]);
    }
}

extern "C" void kernel_launch(void* const* d_in, const int* in_sizes, int n_in,
                              void* d_out, int out_size)
{
    const float* a0 = (const float*)d_in[0];
    const float* a1 = (const float*)d_in[1];
    // x is the large tensor (B*F*K*N), W is F*F — pick by size for safety.
    const float* x = a0; const float* W = a1;
    if (n_in >= 2 && in_sizes[0] < in_sizes[1]) { x = a1; W = a0; }

    dim3 grid(N_ / 32, F_ / 64, B_);   // (64, 8, 8)
    lnkr_fused_kernel<<<grid, 256>>>(x, W, (float*)d_out);
}